// round 14
// baseline (speedup 1.0000x reference)
#include <cuda_runtime.h>
#include <cuda_bf16.h>
#include <cuda_fp16.h>
#include <cstdint>

#define DIMC   256
#define NHEADS 8
#define HDIM   32
#define MAXN   10240   // padded: loaders never read past row 10239
#define MAXE   524288

// Scratch (no cudaMalloc allowed).
__device__ __half g_qh[MAXN * DIMC];   // q in fp16 (gathered per edge)
__device__ float  g_k [MAXN * DIMC];   // k in fp32 (read once per node)
__device__ __half g_vh[MAXN * DIMC];   // v in fp16 (gathered per edge)

// CSR by destination node. g_deg is zero at entry of every kernel_launch:
// statically zero-initialized, and fill_kernel re-zeroes it after use.
__device__ int g_deg[MAXN];
__device__ int g_rowptr[MAXN + 1];
__device__ int g_cursor[MAXN];
__device__ int g_csr[MAXE];

// Pre-split bf16 hi/lo operands in the swizzled smem image.
// Per row: 16 k16-chunks x 4 float4 slots (slot index pre-XORed with row&3).
// Slot s float4 = (hiPair[s], hiPair[s+4], loPair[s], loPair[s+4]).
__device__ float4 gx_s  [MAXN * 64];
__device__ float4 gacc_s[MAXN * 64];   // written directly by edge_csr
__device__ float4 gw_s  [4 * 256 * 64];

// ---------------------------------------------------------------------------
// bf16 split helpers
// ---------------------------------------------------------------------------
__device__ __forceinline__ void split_pair(float a, float b,
                                           uint32_t& hp, uint32_t& lp)
{
    __nv_bfloat16 ha = __float2bfloat16(a);
    __nv_bfloat16 hb = __float2bfloat16(b);
    float la = a - __bfloat162float(ha);
    float lb = b - __bfloat162float(hb);
    __nv_bfloat16 la16 = __float2bfloat16(la);
    __nv_bfloat16 lb16 = __float2bfloat16(lb);
    hp = (uint32_t)__bfloat16_as_ushort(ha) | ((uint32_t)__bfloat16_as_ushort(hb) << 16);
    lp = (uint32_t)__bfloat16_as_ushort(la16) | ((uint32_t)__bfloat16_as_ushort(lb16) << 16);
}

__device__ __forceinline__ void mma_bf16(float* c,
    uint32_t a0, uint32_t a1, uint32_t a2, uint32_t a3,
    uint32_t b0, uint32_t b1)
{
    asm volatile(
        "mma.sync.aligned.m16n8k16.row.col.f32.bf16.bf16.f32 "
        "{%0,%1,%2,%3}, {%4,%5,%6,%7}, {%8,%9}, {%0,%1,%2,%3};"
        : "+f"(c[0]), "+f"(c[1]), "+f"(c[2]), "+f"(c[3])
        : "r"(a0), "r"(a1), "r"(a2), "r"(a3), "r"(b0), "r"(b1));
}

__device__ __forceinline__ void cpa16(uint32_t dst, const void* src) {
    asm volatile("cp.async.ca.shared.global [%0], [%1], 16;" :: "r"(dst), "l"(src));
}

// ---------------------------------------------------------------------------
// Split helper (fp32 row-chunk -> swizzled bf16 hi/lo image).
// ---------------------------------------------------------------------------
__device__ __forceinline__ void split_rowchunk(
    const float* __restrict__ src, float4* __restrict__ dst, int r, int c)
{
    const float4* s = reinterpret_cast<const float4*>(src + (size_t)r * DIMC + c * 16);
    float x[16];
    *reinterpret_cast<float4*>(x + 0)  = s[0];
    *reinterpret_cast<float4*>(x + 4)  = s[1];
    *reinterpret_cast<float4*>(x + 8)  = s[2];
    *reinterpret_cast<float4*>(x + 12) = s[3];
    uint32_t hp[8], lp[8];
#pragma unroll
    for (int t = 0; t < 8; t++) split_pair(x[2 * t], x[2 * t + 1], hp[t], lp[t]);
    float4* d = dst + ((size_t)r * 64 + c * 4);
    int sw = r & 3;
#pragma unroll
    for (int s2 = 0; s2 < 4; s2++)
        d[s2 ^ sw] = make_float4(__uint_as_float(hp[s2]), __uint_as_float(hp[s2 + 4]),
                                 __uint_as_float(lp[s2]), __uint_as_float(lp[s2 + 4]));
}

// ---------------------------------------------------------------------------
// Prep kernel: split(x) + split(W*) + dst-histogram, one launch.
// ---------------------------------------------------------------------------
__global__ void __launch_bounds__(256) prep_kernel(
    const float* __restrict__ x,
    const float* __restrict__ Wq, const float* __restrict__ Wk,
    const float* __restrict__ Wv, const float* __restrict__ Wo,
    const int* __restrict__ dst,
    int N, int E, int splitXBlocks, int splitWBlocks)
{
    int b = blockIdx.x;
    if (b < splitXBlocks) {
        int idx = b * 256 + threadIdx.x;
        if (idx < N * 16) split_rowchunk(x, gx_s, idx >> 4, idx & 15);
    } else if (b < splitXBlocks + splitWBlocks) {
        int idx = (b - splitXBlocks) * 256 + threadIdx.x;
        if (idx < 4 * 256 * 16) {
            int z = idx >> 12;
            int rcl = idx & 4095;
            const float* srcs[4] = {Wq, Wk, Wv, Wo};
            split_rowchunk(srcs[z], gw_s + (size_t)z * 256 * 64, rcl >> 4, rcl & 15);
        }
    } else {
        int e = (b - splitXBlocks - splitWBlocks) * 256 + threadIdx.x;
        if (e < E) atomicAdd(&g_deg[dst[e]], 1);
    }
}

// ---------------------------------------------------------------------------
// CSR build: scan (single CTA) -> fill (+ re-zero g_deg for the next call).
// ---------------------------------------------------------------------------
__global__ void __launch_bounds__(1024) scan_kernel(int N) {
    __shared__ int part[1024];
    int t = threadIdx.x;
    int per = (N + 1023) / 1024;
    int base = t * per;
    int sum = 0;
    for (int i = 0; i < per; i++)
        if (base + i < N) sum += g_deg[base + i];
    part[t] = sum;
    __syncthreads();
    for (int off = 1; off < 1024; off <<= 1) {
        int v = (t >= off) ? part[t - off] : 0;
        __syncthreads();
        part[t] += v;
        __syncthreads();
    }
    int run = part[t] - sum;
    for (int i = 0; i < per; i++) {
        if (base + i < N) {
            g_rowptr[base + i] = run;
            g_cursor[base + i] = run;
            run += g_deg[base + i];
        }
    }
    if (t == 1023) g_rowptr[N] = part[1023];
}

__global__ void __launch_bounds__(256) fill_kernel(
    const int* __restrict__ src, const int* __restrict__ dst,
    int E, int fillBlocks)
{
    int b = blockIdx.x;
    if (b < fillBlocks) {
        int e = b * 256 + threadIdx.x;
        if (e < E) {
            int pos = atomicAdd(&g_cursor[dst[e]], 1);
            g_csr[pos] = src[e];
        }
    } else {
        int i = (b - fillBlocks) * 256 + threadIdx.x;
        if (i < MAXN) g_deg[i] = 0;
    }
}

// ---------------------------------------------------------------------------
// 3xBF16 tensor-core GEMM (m16n8k16), 4-stage cp.async pipeline.
// CTA 128x64, 128 threads, 4 warps with 64x32 warp tiles (halved smem
// traffic per MMA vs 32x32). ~4 CTAs/SM.
// ---------------------------------------------------------------------------
#define BM 128
#define BN 64
#define NCH 16
#define STG 4

template<bool OUT_HALF>
__device__ __forceinline__ void gemm_bf16s(
    const float4* __restrict__ Asrc, int M,
    const float4* __restrict__ Bsrc,
    const float* __restrict__ Bv,
    void* __restrict__ Cv,
    int m0, int n0)
{
    __shared__ float4 As[STG][BM][4];   // 32 KB
    __shared__ float4 Bs[STG][BN][4];   // 16 KB

    int tid  = threadIdx.x;
    int lane = tid & 31;
    int wid  = tid >> 5;                // 0..3
    int wm = (wid & 1) * 64;            // warp m offset (64-row tile)
    int wn = (wid >> 1) * 32;           // warp n offset (32-col tile)
    int gq = lane >> 2;
    int tq = lane & 3;

    // Loaders (128 threads):
    // A: thread -> row = tid, loads all 4 slots (64B).
    // B: thread -> (row = tid>>1, half = tid&1), 2 slots (32B).
    int arow = tid;
    const float4* ap = Asrc + (size_t)(m0 + arow) * 64;
    int brow = tid >> 1, bhalf = tid & 1;
    const float4* bp = Bsrc + (size_t)(n0 + brow) * 64 + bhalf * 2;

    uint32_t sA = (uint32_t)__cvta_generic_to_shared(&As[0][0][0]);
    uint32_t sB = (uint32_t)__cvta_generic_to_shared(&Bs[0][0][0]);
    uint32_t daBase = sA + (uint32_t)(arow * 64);
    uint32_t dbBase = sB + (uint32_t)((brow * 4 + bhalf * 2) * 16);

    float acc[4][4][4];
#pragma unroll
    for (int mi = 0; mi < 4; mi++)
#pragma unroll
        for (int ni = 0; ni < 4; ni++)
#pragma unroll
            for (int j = 0; j < 4; j++) acc[mi][ni][j] = 0.f;

#pragma unroll
    for (int s = 0; s < STG - 1; s++) {
        uint32_t da = daBase + s * (BM * 64);
        uint32_t db = dbBase + s * (BN * 64);
        cpa16(da,      ap + s * 4);
        cpa16(da + 16, ap + s * 4 + 1);
        cpa16(da + 32, ap + s * 4 + 2);
        cpa16(da + 48, ap + s * 4 + 3);
        cpa16(db,      bp + s * 4);
        cpa16(db + 16, bp + s * 4 + 1);
        asm volatile("cp.async.commit_group;");
    }

#pragma unroll 1
    for (int ch = 0; ch < NCH; ch++) {
        asm volatile("cp.async.wait_group %0;" :: "n"(STG - 2) : "memory");
        __syncthreads();
        int st = ch & (STG - 1);

        // B fragments for all 4 ni (16 regs), reused by every mi.
        float4 bfv[4];
#pragma unroll
        for (int ni = 0; ni < 4; ni++) {
            int rn = wn + ni * 8 + gq;
            bfv[ni] = Bs[st][rn][tq ^ (rn & 3)];
        }

#pragma unroll
        for (int mi = 0; mi < 4; mi++) {
            int r0 = wm + mi * 16 + gq;
            float4 af0 = As[st][r0][tq ^ (r0 & 3)];
            float4 af1 = As[st][r0 + 8][tq ^ (r0 & 3)];
            uint32_t a0h = __float_as_uint(af0.x);
            uint32_t a1h = __float_as_uint(af1.x);
            uint32_t a2h = __float_as_uint(af0.y);
            uint32_t a3h = __float_as_uint(af1.y);
            uint32_t a0l = __float_as_uint(af0.z);
            uint32_t a1l = __float_as_uint(af1.z);
            uint32_t a2l = __float_as_uint(af0.w);
            uint32_t a3l = __float_as_uint(af1.w);
#pragma unroll
            for (int ni = 0; ni < 4; ni++) {
                uint32_t b0h = __float_as_uint(bfv[ni].x);
                uint32_t b1h = __float_as_uint(bfv[ni].y);
                uint32_t b0l = __float_as_uint(bfv[ni].z);
                uint32_t b1l = __float_as_uint(bfv[ni].w);
                mma_bf16(acc[mi][ni], a0h, a1h, a2h, a3h, b0h, b1h);
                mma_bf16(acc[mi][ni], a0h, a1h, a2h, a3h, b0l, b1l);
                mma_bf16(acc[mi][ni], a0l, a1l, a2l, a3l, b0h, b1h);
            }
        }

        int nc = ch + STG - 1;
        if (nc < NCH) {
            int ns = nc & (STG - 1);
            uint32_t da = daBase + ns * (BM * 64);
            uint32_t db = dbBase + ns * (BN * 64);
            cpa16(da,      ap + nc * 4);
            cpa16(da + 16, ap + nc * 4 + 1);
            cpa16(da + 32, ap + nc * 4 + 2);
            cpa16(da + 48, ap + nc * 4 + 3);
            cpa16(db,      bp + nc * 4);
            cpa16(db + 16, bp + nc * 4 + 1);
        }
        asm volatile("cp.async.commit_group;");
    }

#pragma unroll
    for (int mi = 0; mi < 4; mi++) {
#pragma unroll
        for (int ni = 0; ni < 4; ni++) {
            int r0 = m0 + wm + mi * 16 + gq;
            int cc = n0 + wn + ni * 8 + 2 * tq;
            float2 bb = *reinterpret_cast<const float2*>(Bv + cc);
            float2 o0 = make_float2(acc[mi][ni][0] + bb.x, acc[mi][ni][1] + bb.y);
            float2 o1 = make_float2(acc[mi][ni][2] + bb.x, acc[mi][ni][3] + bb.y);
            if (OUT_HALF) {
                __half* C = (__half*)Cv;
                if (r0 < M)
                    *reinterpret_cast<__half2*>(C + (size_t)r0 * DIMC + cc) =
                        __floats2half2_rn(o0.x, o0.y);
                if (r0 + 8 < M)
                    *reinterpret_cast<__half2*>(C + (size_t)(r0 + 8) * DIMC + cc) =
                        __floats2half2_rn(o1.x, o1.y);
            } else {
                float* C = (float*)Cv;
                if (r0 < M)
                    *reinterpret_cast<float2*>(C + (size_t)r0 * DIMC + cc) = o0;
                if (r0 + 8 < M)
                    *reinterpret_cast<float2*>(C + (size_t)(r0 + 8) * DIMC + cc) = o1;
            }
        }
    }
}

__global__ void __launch_bounds__(128, 4) gemm_qkv_kernel(
    int M,
    const float* __restrict__ bq, const float* __restrict__ bk,
    const float* __restrict__ bv)
{
    int z = blockIdx.z;
    int m0 = blockIdx.y * BM, n0 = blockIdx.x * BN;
    if (z == 0)
        gemm_bf16s<true >(gx_s, M, gw_s,                         bq, g_qh, m0, n0);
    else if (z == 1)
        gemm_bf16s<false>(gx_s, M, gw_s + (size_t)1 * 256 * 64,  bk, g_k,  m0, n0);
    else
        gemm_bf16s<true >(gx_s, M, gw_s + (size_t)2 * 256 * 64,  bv, g_vh, m0, n0);
}

__global__ void __launch_bounds__(128, 4) gemm_out_kernel(
    int M, const float* __restrict__ bo, float* __restrict__ out)
{
    gemm_bf16s<false>(gacc_s, M, gw_s + (size_t)3 * 256 * 64, bo, out,
                      blockIdx.y * BM, blockIdx.x * BN);
}

// ---------------------------------------------------------------------------
// Edge kernel, dst-centric: one warp per destination node, fp16 q/v gathers,
// fp32 k. Epilogue writes the swizzled bf16 hi/lo split image directly.
// ---------------------------------------------------------------------------
__device__ __forceinline__ float4 h4_to_f4(uint2 u) {
    __half2 a = *reinterpret_cast<__half2*>(&u.x);
    __half2 b = *reinterpret_cast<__half2*>(&u.y);
    float2 fa = __half22float2(a);
    float2 fb = __half22float2(b);
    return make_float4(fa.x, fa.y, fb.x, fb.y);
}

__device__ __forceinline__ void write_split_half(
    int row, int lane, int base_chunk, float4 a)
{
    uint32_t hpA, lpA, hpB, lpB;
    split_pair(a.x, a.y, hpA, lpA);
    split_pair(a.z, a.w, hpB, lpB);
    uint32_t ehpA = __shfl_xor_sync(0xffffffffu, hpA, 2);
    uint32_t elpA = __shfl_xor_sync(0xffffffffu, lpA, 2);
    uint32_t ehpB = __shfl_xor_sync(0xffffffffu, hpB, 2);
    uint32_t elpB = __shfl_xor_sync(0xffffffffu, lpB, 2);
    int c = base_chunk + (lane >> 2);
    bool low = (lane & 2) == 0;
    int s = low ? 2 * (lane & 3) : 2 * (lane & 3) - 3;
    float4 slot = low
        ? make_float4(__uint_as_float(hpA), __uint_as_float(ehpA),
                      __uint_as_float(lpA), __uint_as_float(elpA))
        : make_float4(__uint_as_float(ehpB), __uint_as_float(hpB),
                      __uint_as_float(elpB), __uint_as_float(lpB));
    gacc_s[(size_t)row * 64 + c * 4 + (s ^ (row & 3))] = slot;
}

__global__ void __launch_bounds__(256) edge_csr_kernel(int N)
{
    int node = blockIdx.x * 8 + (threadIdx.x >> 5);
    if (node >= N) return;
    int lane = threadIdx.x & 31;

    const float4* kp = reinterpret_cast<const float4*>(g_k + (size_t)node * DIMC);
    float4 k0 = kp[lane];
    float4 k1 = kp[lane + 32];

    float4 a0 = make_float4(0.f, 0.f, 0.f, 0.f);
    float4 a1 = make_float4(0.f, 0.f, 0.f, 0.f);

    int beg = g_rowptr[node];
    int end = g_rowptr[node + 1];

    const float scale = 0.17677669529663687f;     // 1/sqrt(32)
    const float LOG2E = 1.4426950408889634f;

    if (beg < end) {
        int s = g_csr[beg];
        const uint2* qp = reinterpret_cast<const uint2*>(g_qh + (size_t)s * DIMC);
        const uint2* vp = reinterpret_cast<const uint2*>(g_vh + (size_t)s * DIMC);
        uint2 qr0 = qp[lane], qr1 = qp[lane + 32];
        uint2 vr0 = vp[lane], vr1 = vp[lane + 32];

#pragma unroll 1
        for (int j = beg; j < end; j++) {
            int s2 = (j + 1 < end) ? g_csr[j + 1] : s;
            const uint2* qp2 = reinterpret_cast<const uint2*>(g_qh + (size_t)s2 * DIMC);
            const uint2* vp2 = reinterpret_cast<const uint2*>(g_vh + (size_t)s2 * DIMC);
            uint2 nq0 = qp2[lane], nq1 = qp2[lane + 32];
            uint2 nv0 = vp2[lane], nv1 = vp2[lane + 32];

            float4 q0 = h4_to_f4(qr0), q1 = h4_to_f4(qr1);

            float p0 = q0.x * k0.x + q0.y * k0.y + q0.z * k0.z + q0.w * k0.w;
            float p1 = q1.x * k1.x + q1.y * k1.y + q1.z * k1.z + q1.w * k1.w;
#pragma unroll
            for (int m = 1; m <= 4; m <<= 1) {
                p0 += __shfl_xor_sync(0xffffffffu, p0, m);
                p1 += __shfl_xor_sync(0xffffffffu, p1, m);
            }
            float sc0 = p0 * scale;
            float sc1 = p1 * scale;

            float mx = fmaxf(sc0, sc1);
#pragma unroll
            for (int m = 1; m <= 16; m <<= 1)
                mx = fmaxf(mx, __shfl_xor_sync(0xffffffffu, mx, m));

            float e0 = exp2f((sc0 - mx) * LOG2E);
            float e1 = exp2f((sc1 - mx) * LOG2E);

            float t = e0 + e1;
#pragma unroll
            for (int m = 1; m <= 16; m <<= 1)
                t += __shfl_xor_sync(0xffffffffu, t, m);
            float inv = 8.0f / t;

            float w0 = e0 * inv;
            float w1 = e1 * inv;

            float4 v0 = h4_to_f4(vr0), v1 = h4_to_f4(vr1);
            a0.x = fmaf(w0, v0.x, a0.x); a0.y = fmaf(w0, v0.y, a0.y);
            a0.z = fmaf(w0, v0.z, a0.z); a0.w = fmaf(w0, v0.w, a0.w);
            a1.x = fmaf(w1, v1.x, a1.x); a1.y = fmaf(w1, v1.y, a1.y);
            a1.z = fmaf(w1, v1.z, a1.z); a1.w = fmaf(w1, v1.w, a1.w);

            qr0 = nq0; qr1 = nq1; vr0 = nv0; vr1 = nv1;
        }
    }

    write_split_half(node, lane, 0, a0);   // chunks 0..7
    write_split_half(node, lane, 8, a1);   // chunks 8..15
}

// ---------------------------------------------------------------------------
// Launch
// ---------------------------------------------------------------------------
extern "C" void kernel_launch(void* const* d_in, const int* in_sizes, int n_in,
                              void* d_out, int out_size)
{
    const float* x   = (const float*)d_in[0];
    const int*   src = (const int*)  d_in[1];
    const int*   dst = (const int*)  d_in[2];
    const float* Wq  = (const float*)d_in[3];
    const float* bq  = (const float*)d_in[4];
    const float* Wk  = (const float*)d_in[5];
    const float* bk  = (const float*)d_in[6];
    const float* Wv  = (const float*)d_in[7];
    const float* bv  = (const float*)d_in[8];
    const float* Wo  = (const float*)d_in[9];
    const float* bo  = (const float*)d_in[10];
    float* out = (float*)d_out;

    int N = in_sizes[0] / DIMC;
    int E = in_sizes[1];

    int mtiles = (N + BM - 1) / BM;
    int ntiles = DIMC / BN;

    // 1) prep: split x + split W + dst histogram (one launch)
    int splitXBlocks = (N * 16 + 255) / 256;
    int splitWBlocks = (4 * 256 * 16 + 255) / 256;
    int histBlocks   = (E + 255) / 256;
    prep_kernel<<<splitXBlocks + splitWBlocks + histBlocks, 256>>>(
        x, Wq, Wk, Wv, Wo, dst, N, E, splitXBlocks, splitWBlocks);

    // 2) CSR build
    scan_kernel<<<1, 1024>>>(N);
    int fillBlocks = (E + 255) / 256;
    int zeroDegBlocks = (MAXN + 255) / 256;
    fill_kernel<<<fillBlocks + zeroDegBlocks, 256>>>(src, dst, E, fillBlocks);

    // 3) Q/K/V projections (q,v fp16; k fp32)
    {
        dim3 grid(ntiles, mtiles, 3);
        gemm_qkv_kernel<<<grid, 128>>>(N, bq, bk, bv);
    }

    // 4) dst-centric attention, fused split epilogue
    edge_csr_kernel<<<(N + 7) / 8, 256>>>(N);

    // 5) output projection
    {
        dim3 grid(ntiles, mtiles, 1);
        gemm_out_kernel<<<grid, 128>>>(N, bo, out);
    }
}

// round 15
// speedup vs baseline: 1.1603x; 1.1603x over previous
#include <cuda_runtime.h>
#include <cuda_bf16.h>
#include <cuda_fp16.h>
#include <cstdint>

#define DIMC   256
#define NHEADS 8
#define HDIM   32
#define MAXN   10240   // padded: loaders never read past row 10239
#define MAXE   524288

// Scratch (no cudaMalloc allowed).
__device__ __half g_qh[MAXN * DIMC];   // q in fp16 (gathered per edge)
__device__ float  g_k [MAXN * DIMC];   // k in fp32 (read once per node)
__device__ __half g_vh[MAXN * DIMC];   // v in fp16 (gathered per edge)

// CSR by destination node. g_deg is zero at entry of every kernel_launch:
// statically zero-initialized, and the qkv+fill launch re-zeroes it.
__device__ int g_deg[MAXN];
__device__ int g_rowptr[MAXN + 1];
__device__ int g_cursor[MAXN];
__device__ int g_csr[MAXE];

// Persistent-GEMM work-stealing counters (reset in prep each launch).
__device__ int g_qkv_ctr;
__device__ int g_out_ctr;

// Pre-split bf16 hi/lo operands in the swizzled smem image.
// Per row: 16 k16-chunks x 4 float4 slots (slot index pre-XORed with row&3).
// Slot s float4 = (hiPair[s], hiPair[s+4], loPair[s], loPair[s+4]).
__device__ float4 gx_s  [MAXN * 64];
__device__ float4 gacc_s[MAXN * 64];   // written directly by edge_csr
__device__ float4 gw_s  [4 * 256 * 64];

// ---------------------------------------------------------------------------
// bf16 split helpers
// ---------------------------------------------------------------------------
__device__ __forceinline__ void split_pair(float a, float b,
                                           uint32_t& hp, uint32_t& lp)
{
    __nv_bfloat16 ha = __float2bfloat16(a);
    __nv_bfloat16 hb = __float2bfloat16(b);
    float la = a - __bfloat162float(ha);
    float lb = b - __bfloat162float(hb);
    __nv_bfloat16 la16 = __float2bfloat16(la);
    __nv_bfloat16 lb16 = __float2bfloat16(lb);
    hp = (uint32_t)__bfloat16_as_ushort(ha) | ((uint32_t)__bfloat16_as_ushort(hb) << 16);
    lp = (uint32_t)__bfloat16_as_ushort(la16) | ((uint32_t)__bfloat16_as_ushort(lb16) << 16);
}

__device__ __forceinline__ void mma_bf16(float* c,
    uint32_t a0, uint32_t a1, uint32_t a2, uint32_t a3,
    uint32_t b0, uint32_t b1)
{
    asm volatile(
        "mma.sync.aligned.m16n8k16.row.col.f32.bf16.bf16.f32 "
        "{%0,%1,%2,%3}, {%4,%5,%6,%7}, {%8,%9}, {%0,%1,%2,%3};"
        : "+f"(c[0]), "+f"(c[1]), "+f"(c[2]), "+f"(c[3])
        : "r"(a0), "r"(a1), "r"(a2), "r"(a3), "r"(b0), "r"(b1));
}

__device__ __forceinline__ void cpa16(uint32_t dst, const void* src) {
    asm volatile("cp.async.ca.shared.global [%0], [%1], 16;" :: "r"(dst), "l"(src));
}

// ---------------------------------------------------------------------------
// Split helper (fp32 row-chunk -> swizzled bf16 hi/lo image).
// ---------------------------------------------------------------------------
__device__ __forceinline__ void split_rowchunk(
    const float* __restrict__ src, float4* __restrict__ dst, int r, int c)
{
    const float4* s = reinterpret_cast<const float4*>(src + (size_t)r * DIMC + c * 16);
    float x[16];
    *reinterpret_cast<float4*>(x + 0)  = s[0];
    *reinterpret_cast<float4*>(x + 4)  = s[1];
    *reinterpret_cast<float4*>(x + 8)  = s[2];
    *reinterpret_cast<float4*>(x + 12) = s[3];
    uint32_t hp[8], lp[8];
#pragma unroll
    for (int t = 0; t < 8; t++) split_pair(x[2 * t], x[2 * t + 1], hp[t], lp[t]);
    float4* d = dst + ((size_t)r * 64 + c * 4);
    int sw = r & 3;
#pragma unroll
    for (int s2 = 0; s2 < 4; s2++)
        d[s2 ^ sw] = make_float4(__uint_as_float(hp[s2]), __uint_as_float(hp[s2 + 4]),
                                 __uint_as_float(lp[s2]), __uint_as_float(lp[s2 + 4]));
}

// ---------------------------------------------------------------------------
// Prep kernel: split(x) + split(W*) + dst-histogram + counter reset.
// ---------------------------------------------------------------------------
__global__ void __launch_bounds__(256) prep_kernel(
    const float* __restrict__ x,
    const float* __restrict__ Wq, const float* __restrict__ Wk,
    const float* __restrict__ Wv, const float* __restrict__ Wo,
    const int* __restrict__ dst,
    int N, int E, int splitXBlocks, int splitWBlocks)
{
    int b = blockIdx.x;
    if (b == 0 && threadIdx.x == 0) { g_qkv_ctr = 0; g_out_ctr = 0; }
    if (b < splitXBlocks) {
        int idx = b * 256 + threadIdx.x;
        if (idx < N * 16) split_rowchunk(x, gx_s, idx >> 4, idx & 15);
    } else if (b < splitXBlocks + splitWBlocks) {
        int idx = (b - splitXBlocks) * 256 + threadIdx.x;
        if (idx < 4 * 256 * 16) {
            int z = idx >> 12;
            int rcl = idx & 4095;
            const float* srcs[4] = {Wq, Wk, Wv, Wo};
            split_rowchunk(srcs[z], gw_s + (size_t)z * 256 * 64, rcl >> 4, rcl & 15);
        }
    } else {
        int e = (b - splitXBlocks - splitWBlocks) * 256 + threadIdx.x;
        if (e < E) atomicAdd(&g_deg[dst[e]], 1);
    }
}

// ---------------------------------------------------------------------------
// CSR scan (single CTA).
// ---------------------------------------------------------------------------
__global__ void __launch_bounds__(1024) scan_kernel(int N) {
    __shared__ int part[1024];
    int t = threadIdx.x;
    int per = (N + 1023) / 1024;
    int base = t * per;
    int sum = 0;
    for (int i = 0; i < per; i++)
        if (base + i < N) sum += g_deg[base + i];
    part[t] = sum;
    __syncthreads();
    for (int off = 1; off < 1024; off <<= 1) {
        int v = (t >= off) ? part[t - off] : 0;
        __syncthreads();
        part[t] += v;
        __syncthreads();
    }
    int run = part[t] - sum;
    for (int i = 0; i < per; i++) {
        if (base + i < N) {
            g_rowptr[base + i] = run;
            g_cursor[base + i] = run;
            run += g_deg[base + i];
        }
    }
    if (t == 1023) g_rowptr[N] = part[1023];
}

// ---------------------------------------------------------------------------
// 3xBF16 tensor-core GEMM tile (m16n8k16), 4-stage cp.async pipeline.
// Round-13 proven config: CTA 128x64, 256 threads, 8 warps, 32x32 warp tiles.
// Re-entrant (persistent callers loop over tiles).
// ---------------------------------------------------------------------------
#define BM 128
#define BN 64
#define NCH 16
#define STG 4

template<bool OUT_HALF>
__device__ __forceinline__ void gemm_bf16s(
    const float4* __restrict__ Asrc, int M,
    const float4* __restrict__ Bsrc,
    const float* __restrict__ Bv,
    void* __restrict__ Cv,
    int m0, int n0,
    float4 (*As)[BM][4], float4 (*Bs)[BN][4])
{
    int tid  = threadIdx.x;
    int lane = tid & 31;
    int wid  = tid >> 5;
    int wm = (wid & 3) * 32;
    int wn = (wid >> 2) * 32;
    int gq = lane >> 2;
    int tq = lane & 3;

    int arow = tid >> 1, ahalf = tid & 1;
    const float4* ap = Asrc + (size_t)(m0 + arow) * 64 + ahalf * 2;
    int brow = tid >> 2, bslot = tid & 3;
    const float4* bp = Bsrc + (size_t)(n0 + brow) * 64 + bslot;

    uint32_t sA = (uint32_t)__cvta_generic_to_shared(&As[0][0][0]);
    uint32_t sB = (uint32_t)__cvta_generic_to_shared(&Bs[0][0][0]);
    uint32_t daBase = sA + (uint32_t)((arow * 4 + ahalf * 2) * 16);
    uint32_t dbBase = sB + (uint32_t)((brow * 4 + bslot) * 16);

    float acc[2][4][4];
#pragma unroll
    for (int mi = 0; mi < 2; mi++)
#pragma unroll
        for (int ni = 0; ni < 4; ni++)
#pragma unroll
            for (int j = 0; j < 4; j++) acc[mi][ni][j] = 0.f;

#pragma unroll
    for (int s = 0; s < STG - 1; s++) {
        uint32_t da = daBase + s * (BM * 64);
        uint32_t db = dbBase + s * (BN * 64);
        cpa16(da,      ap + s * 4);
        cpa16(da + 16, ap + s * 4 + 1);
        cpa16(db,      bp + s * 4);
        asm volatile("cp.async.commit_group;");
    }

#pragma unroll 1
    for (int ch = 0; ch < NCH; ch++) {
        asm volatile("cp.async.wait_group %0;" :: "n"(STG - 2) : "memory");
        __syncthreads();
        int st = ch & (STG - 1);

        float4 af0[2], af1[2], bfv[4];
#pragma unroll
        for (int mi = 0; mi < 2; mi++) {
            int r0 = wm + mi * 16 + gq;
            af0[mi] = As[st][r0][tq ^ (r0 & 3)];
            af1[mi] = As[st][r0 + 8][tq ^ (r0 & 3)];
        }
#pragma unroll
        for (int ni = 0; ni < 4; ni++) {
            int rn = wn + ni * 8 + gq;
            bfv[ni] = Bs[st][rn][tq ^ (rn & 3)];
        }

#pragma unroll
        for (int mi = 0; mi < 2; mi++) {
            uint32_t a0h = __float_as_uint(af0[mi].x);
            uint32_t a1h = __float_as_uint(af1[mi].x);
            uint32_t a2h = __float_as_uint(af0[mi].y);
            uint32_t a3h = __float_as_uint(af1[mi].y);
            uint32_t a0l = __float_as_uint(af0[mi].z);
            uint32_t a1l = __float_as_uint(af1[mi].z);
            uint32_t a2l = __float_as_uint(af0[mi].w);
            uint32_t a3l = __float_as_uint(af1[mi].w);
#pragma unroll
            for (int ni = 0; ni < 4; ni++) {
                uint32_t b0h = __float_as_uint(bfv[ni].x);
                uint32_t b1h = __float_as_uint(bfv[ni].y);
                uint32_t b0l = __float_as_uint(bfv[ni].z);
                uint32_t b1l = __float_as_uint(bfv[ni].w);
                mma_bf16(acc[mi][ni], a0h, a1h, a2h, a3h, b0h, b1h);
                mma_bf16(acc[mi][ni], a0h, a1h, a2h, a3h, b0l, b1l);
                mma_bf16(acc[mi][ni], a0l, a1l, a2l, a3l, b0h, b1h);
            }
        }

        int nc = ch + STG - 1;
        if (nc < NCH) {
            int ns = nc & (STG - 1);
            uint32_t da = daBase + ns * (BM * 64);
            uint32_t db = dbBase + ns * (BN * 64);
            cpa16(da,      ap + nc * 4);
            cpa16(da + 16, ap + nc * 4 + 1);
            cpa16(db,      bp + nc * 4);
        }
        asm volatile("cp.async.commit_group;");
    }

#pragma unroll
    for (int mi = 0; mi < 2; mi++) {
#pragma unroll
        for (int ni = 0; ni < 4; ni++) {
            int r0 = m0 + wm + mi * 16 + gq;
            int cc = n0 + wn + ni * 8 + 2 * tq;
            float2 bb = *reinterpret_cast<const float2*>(Bv + cc);
            float2 o0 = make_float2(acc[mi][ni][0] + bb.x, acc[mi][ni][1] + bb.y);
            float2 o1 = make_float2(acc[mi][ni][2] + bb.x, acc[mi][ni][3] + bb.y);
            if (OUT_HALF) {
                __half* C = (__half*)Cv;
                if (r0 < M)
                    *reinterpret_cast<__half2*>(C + (size_t)r0 * DIMC + cc) =
                        __floats2half2_rn(o0.x, o0.y);
                if (r0 + 8 < M)
                    *reinterpret_cast<__half2*>(C + (size_t)(r0 + 8) * DIMC + cc) =
                        __floats2half2_rn(o1.x, o1.y);
            } else {
                float* C = (float*)Cv;
                if (r0 < M)
                    *reinterpret_cast<float2*>(C + (size_t)r0 * DIMC + cc) = o0;
                if (r0 + 8 < M)
                    *reinterpret_cast<float2*>(C + (size_t)(r0 + 8) * DIMC + cc) = o1;
            }
        }
    }
}

// ---------------------------------------------------------------------------
// Persistent QKV GEMM + fused CSR fill + g_deg re-zero, one launch.
// Blocks [0, NGEMM): work-stealing GEMM over 3*mtiles*ntiles tiles.
// Blocks [NGEMM, NGEMM+fillBlocks): CSR fill.
// Remaining blocks: re-zero g_deg for the next launch.
// ---------------------------------------------------------------------------
#define NGEMM 304   // 2 CTAs/SM x 152 SMs

__global__ void __launch_bounds__(256, 2) gemm_qkv_fill_kernel(
    int M, int totalTiles,
    const float* __restrict__ bq, const float* __restrict__ bk,
    const float* __restrict__ bv,
    const int* __restrict__ src, const int* __restrict__ dst,
    int E, int fillBlocks)
{
    int b = blockIdx.x;
    if (b >= NGEMM) {
        int fb = b - NGEMM;
        if (fb < fillBlocks) {
            int e = fb * 256 + threadIdx.x;
            if (e < E) {
                int pos = atomicAdd(&g_cursor[dst[e]], 1);
                g_csr[pos] = src[e];
            }
        } else {
            int i = (fb - fillBlocks) * 256 + threadIdx.x;
            if (i < MAXN) g_deg[i] = 0;
        }
        return;
    }

    __shared__ float4 As[STG][BM][4];
    __shared__ float4 Bs[STG][BN][4];
    __shared__ int s_t;

    for (;;) {
        __syncthreads();
        if (threadIdx.x == 0) s_t = atomicAdd(&g_qkv_ctr, 1);
        __syncthreads();
        int t = s_t;
        if (t >= totalTiles) break;
        int z  = t % 3;          // z fastest: consecutive steals share the A tile
        int r  = t / 3;
        int n0 = (r & 3) * BN;
        int m0 = (r >> 2) * BM;
        if (z == 0)
            gemm_bf16s<true >(gx_s, M, gw_s,                        bq, g_qh, m0, n0, As, Bs);
        else if (z == 1)
            gemm_bf16s<false>(gx_s, M, gw_s + (size_t)1 * 256 * 64, bk, g_k,  m0, n0, As, Bs);
        else
            gemm_bf16s<true >(gx_s, M, gw_s + (size_t)2 * 256 * 64, bv, g_vh, m0, n0, As, Bs);
    }
}

// Persistent output projection.
__global__ void __launch_bounds__(256, 2) gemm_out_kernel(
    int M, int totalTiles, const float* __restrict__ bo, float* __restrict__ out)
{
    __shared__ float4 As[STG][BM][4];
    __shared__ float4 Bs[STG][BN][4];
    __shared__ int s_t;

    for (;;) {
        __syncthreads();
        if (threadIdx.x == 0) s_t = atomicAdd(&g_out_ctr, 1);
        __syncthreads();
        int t = s_t;
        if (t >= totalTiles) break;
        int n0 = (t & 3) * BN;
        int m0 = (t >> 2) * BM;
        gemm_bf16s<false>(gacc_s, M, gw_s + (size_t)3 * 256 * 64, bo, out,
                          m0, n0, As, Bs);
    }
}

// ---------------------------------------------------------------------------
// Edge kernel, dst-centric: one warp per destination node, fp16 q/v gathers,
// fp32 k. Epilogue writes the swizzled bf16 hi/lo split image directly.
// ---------------------------------------------------------------------------
__device__ __forceinline__ float4 h4_to_f4(uint2 u) {
    __half2 a = *reinterpret_cast<__half2*>(&u.x);
    __half2 b = *reinterpret_cast<__half2*>(&u.y);
    float2 fa = __half22float2(a);
    float2 fb = __half22float2(b);
    return make_float4(fa.x, fa.y, fb.x, fb.y);
}

__device__ __forceinline__ void write_split_half(
    int row, int lane, int base_chunk, float4 a)
{
    uint32_t hpA, lpA, hpB, lpB;
    split_pair(a.x, a.y, hpA, lpA);
    split_pair(a.z, a.w, hpB, lpB);
    uint32_t ehpA = __shfl_xor_sync(0xffffffffu, hpA, 2);
    uint32_t elpA = __shfl_xor_sync(0xffffffffu, lpA, 2);
    uint32_t ehpB = __shfl_xor_sync(0xffffffffu, hpB, 2);
    uint32_t elpB = __shfl_xor_sync(0xffffffffu, lpB, 2);
    int c = base_chunk + (lane >> 2);
    bool low = (lane & 2) == 0;
    int s = low ? 2 * (lane & 3) : 2 * (lane & 3) - 3;
    float4 slot = low
        ? make_float4(__uint_as_float(hpA), __uint_as_float(ehpA),
                      __uint_as_float(lpA), __uint_as_float(elpA))
        : make_float4(__uint_as_float(ehpB), __uint_as_float(hpB),
                      __uint_as_float(elpB), __uint_as_float(lpB));
    gacc_s[(size_t)row * 64 + c * 4 + (s ^ (row & 3))] = slot;
}

__global__ void __launch_bounds__(256) edge_csr_kernel(int N)
{
    int node = blockIdx.x * 8 + (threadIdx.x >> 5);
    if (node >= N) return;
    int lane = threadIdx.x & 31;

    const float4* kp = reinterpret_cast<const float4*>(g_k + (size_t)node * DIMC);
    float4 k0 = kp[lane];
    float4 k1 = kp[lane + 32];

    float4 a0 = make_float4(0.f, 0.f, 0.f, 0.f);
    float4 a1 = make_float4(0.f, 0.f, 0.f, 0.f);

    int beg = g_rowptr[node];
    int end = g_rowptr[node + 1];

    const float scale = 0.17677669529663687f;     // 1/sqrt(32)
    const float LOG2E = 1.4426950408889634f;

    if (beg < end) {
        int s = g_csr[beg];
        const uint2* qp = reinterpret_cast<const uint2*>(g_qh + (size_t)s * DIMC);
        const uint2* vp = reinterpret_cast<const uint2*>(g_vh + (size_t)s * DIMC);
        uint2 qr0 = qp[lane], qr1 = qp[lane + 32];
        uint2 vr0 = vp[lane], vr1 = vp[lane + 32];

#pragma unroll 1
        for (int j = beg; j < end; j++) {
            int s2 = (j + 1 < end) ? g_csr[j + 1] : s;
            const uint2* qp2 = reinterpret_cast<const uint2*>(g_qh + (size_t)s2 * DIMC);
            const uint2* vp2 = reinterpret_cast<const uint2*>(g_vh + (size_t)s2 * DIMC);
            uint2 nq0 = qp2[lane], nq1 = qp2[lane + 32];
            uint2 nv0 = vp2[lane], nv1 = vp2[lane + 32];

            float4 q0 = h4_to_f4(qr0), q1 = h4_to_f4(qr1);

            float p0 = q0.x * k0.x + q0.y * k0.y + q0.z * k0.z + q0.w * k0.w;
            float p1 = q1.x * k1.x + q1.y * k1.y + q1.z * k1.z + q1.w * k1.w;
#pragma unroll
            for (int m = 1; m <= 4; m <<= 1) {
                p0 += __shfl_xor_sync(0xffffffffu, p0, m);
                p1 += __shfl_xor_sync(0xffffffffu, p1, m);
            }
            float sc0 = p0 * scale;
            float sc1 = p1 * scale;

            float mx = fmaxf(sc0, sc1);
#pragma unroll
            for (int m = 1; m <= 16; m <<= 1)
                mx = fmaxf(mx, __shfl_xor_sync(0xffffffffu, mx, m));

            float e0 = exp2f((sc0 - mx) * LOG2E);
            float e1 = exp2f((sc1 - mx) * LOG2E);

            float t = e0 + e1;
#pragma unroll
            for (int m = 1; m <= 16; m <<= 1)
                t += __shfl_xor_sync(0xffffffffu, t, m);
            float inv = 8.0f / t;

            float w0 = e0 * inv;
            float w1 = e1 * inv;

            float4 v0 = h4_to_f4(vr0), v1 = h4_to_f4(vr1);
            a0.x = fmaf(w0, v0.x, a0.x); a0.y = fmaf(w0, v0.y, a0.y);
            a0.z = fmaf(w0, v0.z, a0.z); a0.w = fmaf(w0, v0.w, a0.w);
            a1.x = fmaf(w1, v1.x, a1.x); a1.y = fmaf(w1, v1.y, a1.y);
            a1.z = fmaf(w1, v1.z, a1.z); a1.w = fmaf(w1, v1.w, a1.w);

            qr0 = nq0; qr1 = nq1; vr0 = nv0; vr1 = nv1;
        }
    }

    write_split_half(node, lane, 0, a0);   // chunks 0..7
    write_split_half(node, lane, 8, a1);   // chunks 8..15
}

// ---------------------------------------------------------------------------
// Launch
// ---------------------------------------------------------------------------
extern "C" void kernel_launch(void* const* d_in, const int* in_sizes, int n_in,
                              void* d_out, int out_size)
{
    const float* x   = (const float*)d_in[0];
    const int*   src = (const int*)  d_in[1];
    const int*   dst = (const int*)  d_in[2];
    const float* Wq  = (const float*)d_in[3];
    const float* bq  = (const float*)d_in[4];
    const float* Wk  = (const float*)d_in[5];
    const float* bk  = (const float*)d_in[6];
    const float* Wv  = (const float*)d_in[7];
    const float* bv  = (const float*)d_in[8];
    const float* Wo  = (const float*)d_in[9];
    const float* bo  = (const float*)d_in[10];
    float* out = (float*)d_out;

    int N = in_sizes[0] / DIMC;
    int E = in_sizes[1];

    int mtiles = (N + BM - 1) / BM;   // 79
    int ntiles = DIMC / BN;           // 4

    // 1) prep: split x + split W + dst histogram + counter reset (one launch)
    int splitXBlocks = (N * 16 + 255) / 256;
    int splitWBlocks = (4 * 256 * 16 + 255) / 256;
    int histBlocks   = (E + 255) / 256;
    prep_kernel<<<splitXBlocks + splitWBlocks + histBlocks, 256>>>(
        x, Wq, Wk, Wv, Wo, dst, N, E, splitXBlocks, splitWBlocks);

    // 2) CSR scan
    scan_kernel<<<1, 1024>>>(N);

    // 3) persistent QKV GEMM + fused CSR fill + deg re-zero (one launch)
    int fillBlocks    = (E + 255) / 256;
    int zeroDegBlocks = (MAXN + 255) / 256;
    int qkvTiles = 3 * mtiles * ntiles;
    gemm_qkv_fill_kernel<<<NGEMM + fillBlocks + zeroDegBlocks, 256>>>(
        N, qkvTiles, bq, bk, bv, src, dst, E, fillBlocks);

    // 4) dst-centric attention, fused split epilogue
    edge_csr_kernel<<<(N + 7) / 8, 256>>>(N);

    // 5) persistent output projection
    gemm_out_kernel<<<NGEMM, 256>>>(N, mtiles * ntiles, bo, out);
}

// round 16
// speedup vs baseline: 1.2794x; 1.1026x over previous
#include <cuda_runtime.h>
#include <cuda_bf16.h>
#include <cuda_fp16.h>
#include <cstdint>

#define DIMC   256
#define NHEADS 8
#define HDIM   32
#define MAXN   10240   // padded: loaders never read past row 10239
#define MAXE   524288

// Scratch (no cudaMalloc allowed).
__device__ __half g_qh[MAXN * DIMC];   // q in fp16 (gathered per edge)
__device__ float  g_k [MAXN * DIMC];   // k in fp32 (read once per node)
__device__ __half g_vh[MAXN * DIMC];   // v in fp16 (gathered per edge)

// CSR by destination node. g_deg is zero at entry of every kernel_launch:
// statically zero-initialized, and the qkv+fill launch re-zeroes it.
__device__ int g_deg[MAXN];
__device__ int g_rowptr[MAXN + 1];
__device__ int g_cursor[MAXN];
__device__ int g_csr[MAXE];

// Persistent-GEMM work-stealing counters (reset in prep each launch).
__device__ int g_qkv_ctr;
__device__ int g_out_ctr;

// Pre-split bf16 hi/lo operands in the swizzled smem image.
// Per row: 16 k16-chunks x 4 float4 slots (slot index pre-XORed with row&3).
// Slot s float4 = (hiPair[s], hiPair[s+4], loPair[s], loPair[s+4]).
__device__ float4 gx_s  [MAXN * 64];
__device__ float4 gacc_s[MAXN * 64];   // written directly by edge_csr
__device__ float4 gw_s  [4 * 256 * 64];

// ---------------------------------------------------------------------------
// bf16 split helpers
// ---------------------------------------------------------------------------
__device__ __forceinline__ void split_pair(float a, float b,
                                           uint32_t& hp, uint32_t& lp)
{
    __nv_bfloat16 ha = __float2bfloat16(a);
    __nv_bfloat16 hb = __float2bfloat16(b);
    float la = a - __bfloat162float(ha);
    float lb = b - __bfloat162float(hb);
    __nv_bfloat16 la16 = __float2bfloat16(la);
    __nv_bfloat16 lb16 = __float2bfloat16(lb);
    hp = (uint32_t)__bfloat16_as_ushort(ha) | ((uint32_t)__bfloat16_as_ushort(hb) << 16);
    lp = (uint32_t)__bfloat16_as_ushort(la16) | ((uint32_t)__bfloat16_as_ushort(lb16) << 16);
}

__device__ __forceinline__ void mma_bf16(float* c,
    uint32_t a0, uint32_t a1, uint32_t a2, uint32_t a3,
    uint32_t b0, uint32_t b1)
{
    asm volatile(
        "mma.sync.aligned.m16n8k16.row.col.f32.bf16.bf16.f32 "
        "{%0,%1,%2,%3}, {%4,%5,%6,%7}, {%8,%9}, {%0,%1,%2,%3};"
        : "+f"(c[0]), "+f"(c[1]), "+f"(c[2]), "+f"(c[3])
        : "r"(a0), "r"(a1), "r"(a2), "r"(a3), "r"(b0), "r"(b1));
}

__device__ __forceinline__ void cpa16(uint32_t dst, const void* src) {
    asm volatile("cp.async.ca.shared.global [%0], [%1], 16;" :: "r"(dst), "l"(src));
}

// ---------------------------------------------------------------------------
// Split helper (fp32 row-chunk -> swizzled bf16 hi/lo image).
// ---------------------------------------------------------------------------
__device__ __forceinline__ void split_rowchunk(
    const float* __restrict__ src, float4* __restrict__ dst, int r, int c)
{
    const float4* s = reinterpret_cast<const float4*>(src + (size_t)r * DIMC + c * 16);
    float x[16];
    *reinterpret_cast<float4*>(x + 0)  = s[0];
    *reinterpret_cast<float4*>(x + 4)  = s[1];
    *reinterpret_cast<float4*>(x + 8)  = s[2];
    *reinterpret_cast<float4*>(x + 12) = s[3];
    uint32_t hp[8], lp[8];
#pragma unroll
    for (int t = 0; t < 8; t++) split_pair(x[2 * t], x[2 * t + 1], hp[t], lp[t]);
    float4* d = dst + ((size_t)r * 64 + c * 4);
    int sw = r & 3;
#pragma unroll
    for (int s2 = 0; s2 < 4; s2++)
        d[s2 ^ sw] = make_float4(__uint_as_float(hp[s2]), __uint_as_float(hp[s2 + 4]),
                                 __uint_as_float(lp[s2]), __uint_as_float(lp[s2 + 4]));
}

// ---------------------------------------------------------------------------
// Prep kernel: split(x) + split(W*) + dst-histogram + counter reset.
// ---------------------------------------------------------------------------
__global__ void __launch_bounds__(256) prep_kernel(
    const float* __restrict__ x,
    const float* __restrict__ Wq, const float* __restrict__ Wk,
    const float* __restrict__ Wv, const float* __restrict__ Wo,
    const int* __restrict__ dst,
    int N, int E, int splitXBlocks, int splitWBlocks)
{
    int b = blockIdx.x;
    if (b == 0 && threadIdx.x == 0) { g_qkv_ctr = 0; g_out_ctr = 0; }
    if (b < splitXBlocks) {
        int idx = b * 256 + threadIdx.x;
        if (idx < N * 16) split_rowchunk(x, gx_s, idx >> 4, idx & 15);
    } else if (b < splitXBlocks + splitWBlocks) {
        int idx = (b - splitXBlocks) * 256 + threadIdx.x;
        if (idx < 4 * 256 * 16) {
            int z = idx >> 12;
            int rcl = idx & 4095;
            const float* srcs[4] = {Wq, Wk, Wv, Wo};
            split_rowchunk(srcs[z], gw_s + (size_t)z * 256 * 64, rcl >> 4, rcl & 15);
        }
    } else {
        int e = (b - splitXBlocks - splitWBlocks) * 256 + threadIdx.x;
        if (e < E) atomicAdd(&g_deg[dst[e]], 1);
    }
}

// ---------------------------------------------------------------------------
// CSR scan (single CTA).
// ---------------------------------------------------------------------------
__global__ void __launch_bounds__(1024) scan_kernel(int N) {
    __shared__ int part[1024];
    int t = threadIdx.x;
    int per = (N + 1023) / 1024;
    int base = t * per;
    int sum = 0;
    for (int i = 0; i < per; i++)
        if (base + i < N) sum += g_deg[base + i];
    part[t] = sum;
    __syncthreads();
    for (int off = 1; off < 1024; off <<= 1) {
        int v = (t >= off) ? part[t - off] : 0;
        __syncthreads();
        part[t] += v;
        __syncthreads();
    }
    int run = part[t] - sum;
    for (int i = 0; i < per; i++) {
        if (base + i < N) {
            g_rowptr[base + i] = run;
            g_cursor[base + i] = run;
            run += g_deg[base + i];
        }
    }
    if (t == 1023) g_rowptr[N] = part[1023];
}

// ---------------------------------------------------------------------------
// 3xBF16 tensor-core GEMM tile (m16n8k16), 4-stage cp.async pipeline.
// Round-13 proven config: CTA 128x64, 256 threads, 8 warps, 32x32 warp tiles.
// Re-entrant (persistent callers loop over tiles).
// ---------------------------------------------------------------------------
#define BM 128
#define BN 64
#define NCH 16
#define STG 4

template<bool OUT_HALF>
__device__ __forceinline__ void gemm_bf16s(
    const float4* __restrict__ Asrc, int M,
    const float4* __restrict__ Bsrc,
    const float* __restrict__ Bv,
    void* __restrict__ Cv,
    int m0, int n0,
    float4 (*As)[BM][4], float4 (*Bs)[BN][4])
{
    int tid  = threadIdx.x;
    int lane = tid & 31;
    int wid  = tid >> 5;
    int wm = (wid & 3) * 32;
    int wn = (wid >> 2) * 32;
    int gq = lane >> 2;
    int tq = lane & 3;

    int arow = tid >> 1, ahalf = tid & 1;
    const float4* ap = Asrc + (size_t)(m0 + arow) * 64 + ahalf * 2;
    int brow = tid >> 2, bslot = tid & 3;
    const float4* bp = Bsrc + (size_t)(n0 + brow) * 64 + bslot;

    uint32_t sA = (uint32_t)__cvta_generic_to_shared(&As[0][0][0]);
    uint32_t sB = (uint32_t)__cvta_generic_to_shared(&Bs[0][0][0]);
    uint32_t daBase = sA + (uint32_t)((arow * 4 + ahalf * 2) * 16);
    uint32_t dbBase = sB + (uint32_t)((brow * 4 + bslot) * 16);

    float acc[2][4][4];
#pragma unroll
    for (int mi = 0; mi < 2; mi++)
#pragma unroll
        for (int ni = 0; ni < 4; ni++)
#pragma unroll
            for (int j = 0; j < 4; j++) acc[mi][ni][j] = 0.f;

#pragma unroll
    for (int s = 0; s < STG - 1; s++) {
        uint32_t da = daBase + s * (BM * 64);
        uint32_t db = dbBase + s * (BN * 64);
        cpa16(da,      ap + s * 4);
        cpa16(da + 16, ap + s * 4 + 1);
        cpa16(db,      bp + s * 4);
        asm volatile("cp.async.commit_group;");
    }

#pragma unroll 1
    for (int ch = 0; ch < NCH; ch++) {
        asm volatile("cp.async.wait_group %0;" :: "n"(STG - 2) : "memory");
        __syncthreads();
        int st = ch & (STG - 1);

        float4 af0[2], af1[2], bfv[4];
#pragma unroll
        for (int mi = 0; mi < 2; mi++) {
            int r0 = wm + mi * 16 + gq;
            af0[mi] = As[st][r0][tq ^ (r0 & 3)];
            af1[mi] = As[st][r0 + 8][tq ^ (r0 & 3)];
        }
#pragma unroll
        for (int ni = 0; ni < 4; ni++) {
            int rn = wn + ni * 8 + gq;
            bfv[ni] = Bs[st][rn][tq ^ (rn & 3)];
        }

#pragma unroll
        for (int mi = 0; mi < 2; mi++) {
            uint32_t a0h = __float_as_uint(af0[mi].x);
            uint32_t a1h = __float_as_uint(af1[mi].x);
            uint32_t a2h = __float_as_uint(af0[mi].y);
            uint32_t a3h = __float_as_uint(af1[mi].y);
            uint32_t a0l = __float_as_uint(af0[mi].z);
            uint32_t a1l = __float_as_uint(af1[mi].z);
            uint32_t a2l = __float_as_uint(af0[mi].w);
            uint32_t a3l = __float_as_uint(af1[mi].w);
#pragma unroll
            for (int ni = 0; ni < 4; ni++) {
                uint32_t b0h = __float_as_uint(bfv[ni].x);
                uint32_t b1h = __float_as_uint(bfv[ni].y);
                uint32_t b0l = __float_as_uint(bfv[ni].z);
                uint32_t b1l = __float_as_uint(bfv[ni].w);
                mma_bf16(acc[mi][ni], a0h, a1h, a2h, a3h, b0h, b1h);
                mma_bf16(acc[mi][ni], a0h, a1h, a2h, a3h, b0l, b1l);
                mma_bf16(acc[mi][ni], a0l, a1l, a2l, a3l, b0h, b1h);
            }
        }

        int nc = ch + STG - 1;
        if (nc < NCH) {
            int ns = nc & (STG - 1);
            uint32_t da = daBase + ns * (BM * 64);
            uint32_t db = dbBase + ns * (BN * 64);
            cpa16(da,      ap + nc * 4);
            cpa16(da + 16, ap + nc * 4 + 1);
            cpa16(db,      bp + nc * 4);
        }
        asm volatile("cp.async.commit_group;");
    }

#pragma unroll
    for (int mi = 0; mi < 2; mi++) {
#pragma unroll
        for (int ni = 0; ni < 4; ni++) {
            int r0 = m0 + wm + mi * 16 + gq;
            int cc = n0 + wn + ni * 8 + 2 * tq;
            float2 bb = *reinterpret_cast<const float2*>(Bv + cc);
            float2 o0 = make_float2(acc[mi][ni][0] + bb.x, acc[mi][ni][1] + bb.y);
            float2 o1 = make_float2(acc[mi][ni][2] + bb.x, acc[mi][ni][3] + bb.y);
            if (OUT_HALF) {
                __half* C = (__half*)Cv;
                if (r0 < M)
                    *reinterpret_cast<__half2*>(C + (size_t)r0 * DIMC + cc) =
                        __floats2half2_rn(o0.x, o0.y);
                if (r0 + 8 < M)
                    *reinterpret_cast<__half2*>(C + (size_t)(r0 + 8) * DIMC + cc) =
                        __floats2half2_rn(o1.x, o1.y);
            } else {
                float* C = (float*)Cv;
                if (r0 < M)
                    *reinterpret_cast<float2*>(C + (size_t)r0 * DIMC + cc) = o0;
                if (r0 + 8 < M)
                    *reinterpret_cast<float2*>(C + (size_t)(r0 + 8) * DIMC + cc) = o1;
            }
        }
    }
}

// ---------------------------------------------------------------------------
// Persistent QKV GEMM + fused CSR fill + g_deg re-zero, one launch.
// ---------------------------------------------------------------------------
#define NGEMM 304   // 2 CTAs/SM x 152 SMs

__global__ void __launch_bounds__(256, 2) gemm_qkv_fill_kernel(
    int M, int totalTiles,
    const float* __restrict__ bq, const float* __restrict__ bk,
    const float* __restrict__ bv,
    const int* __restrict__ src, const int* __restrict__ dst,
    int E, int fillBlocks)
{
    int b = blockIdx.x;
    if (b >= NGEMM) {
        int fb = b - NGEMM;
        if (fb < fillBlocks) {
            int e = fb * 256 + threadIdx.x;
            if (e < E) {
                int pos = atomicAdd(&g_cursor[dst[e]], 1);
                g_csr[pos] = src[e];
            }
        } else {
            int i = (fb - fillBlocks) * 256 + threadIdx.x;
            if (i < MAXN) g_deg[i] = 0;
        }
        return;
    }

    __shared__ float4 As[STG][BM][4];
    __shared__ float4 Bs[STG][BN][4];
    __shared__ int s_t;

    for (;;) {
        __syncthreads();
        if (threadIdx.x == 0) s_t = atomicAdd(&g_qkv_ctr, 1);
        __syncthreads();
        int t = s_t;
        if (t >= totalTiles) break;
        int z  = t % 3;          // z fastest: consecutive steals share the A tile
        int r  = t / 3;
        int n0 = (r & 3) * BN;
        int m0 = (r >> 2) * BM;
        if (z == 0)
            gemm_bf16s<true >(gx_s, M, gw_s,                        bq, g_qh, m0, n0, As, Bs);
        else if (z == 1)
            gemm_bf16s<false>(gx_s, M, gw_s + (size_t)1 * 256 * 64, bk, g_k,  m0, n0, As, Bs);
        else
            gemm_bf16s<true >(gx_s, M, gw_s + (size_t)2 * 256 * 64, bv, g_vh, m0, n0, As, Bs);
    }
}

// Persistent output projection.
__global__ void __launch_bounds__(256, 2) gemm_out_kernel(
    int M, int totalTiles, const float* __restrict__ bo, float* __restrict__ out)
{
    __shared__ float4 As[STG][BM][4];
    __shared__ float4 Bs[STG][BN][4];
    __shared__ int s_t;

    for (;;) {
        __syncthreads();
        if (threadIdx.x == 0) s_t = atomicAdd(&g_out_ctr, 1);
        __syncthreads();
        int t = s_t;
        if (t >= totalTiles) break;
        int n0 = (t & 3) * BN;
        int m0 = (t >> 2) * BM;
        gemm_bf16s<false>(gacc_s, M, gw_s + (size_t)3 * 256 * 64, bo, out,
                          m0, n0, As, Bs);
    }
}

// ---------------------------------------------------------------------------
// Edge kernel, dst-centric: one warp per destination node, fp16 q/v gathers,
// fp32 k. Lean softmax: no max-subtraction (scores are O(1); exp2 cannot
// overflow), and the head-sum needs only 2 shuffles because e0+e1 is already
// uniform within each aligned 8-lane group after the dot reduction.
// ---------------------------------------------------------------------------
__device__ __forceinline__ float4 h4_to_f4(uint2 u) {
    __half2 a = *reinterpret_cast<__half2*>(&u.x);
    __half2 b = *reinterpret_cast<__half2*>(&u.y);
    float2 fa = __half22float2(a);
    float2 fb = __half22float2(b);
    return make_float4(fa.x, fa.y, fb.x, fb.y);
}

__device__ __forceinline__ void write_split_half(
    int row, int lane, int base_chunk, float4 a)
{
    uint32_t hpA, lpA, hpB, lpB;
    split_pair(a.x, a.y, hpA, lpA);
    split_pair(a.z, a.w, hpB, lpB);
    uint32_t ehpA = __shfl_xor_sync(0xffffffffu, hpA, 2);
    uint32_t elpA = __shfl_xor_sync(0xffffffffu, lpA, 2);
    uint32_t ehpB = __shfl_xor_sync(0xffffffffu, hpB, 2);
    uint32_t elpB = __shfl_xor_sync(0xffffffffu, lpB, 2);
    int c = base_chunk + (lane >> 2);
    bool low = (lane & 2) == 0;
    int s = low ? 2 * (lane & 3) : 2 * (lane & 3) - 3;
    float4 slot = low
        ? make_float4(__uint_as_float(hpA), __uint_as_float(ehpA),
                      __uint_as_float(lpA), __uint_as_float(elpA))
        : make_float4(__uint_as_float(ehpB), __uint_as_float(hpB),
                      __uint_as_float(elpB), __uint_as_float(lpB));
    gacc_s[(size_t)row * 64 + c * 4 + (s ^ (row & 3))] = slot;
}

__global__ void __launch_bounds__(256) edge_csr_kernel(int N)
{
    int node = blockIdx.x * 8 + (threadIdx.x >> 5);
    if (node >= N) return;
    int lane = threadIdx.x & 31;

    const float4* kp = reinterpret_cast<const float4*>(g_k + (size_t)node * DIMC);
    float4 k0 = kp[lane];
    float4 k1 = kp[lane + 32];

    float4 a0 = make_float4(0.f, 0.f, 0.f, 0.f);
    float4 a1 = make_float4(0.f, 0.f, 0.f, 0.f);

    int beg = g_rowptr[node];
    int end = g_rowptr[node + 1];

    // exp(score) = exp2(p * scale * log2(e)); scores O(1) so no max needed.
    const float cexp = 0.17677669529663687f * 1.4426950408889634f;

    if (beg < end) {
        int s = g_csr[beg];
        const uint2* qp = reinterpret_cast<const uint2*>(g_qh + (size_t)s * DIMC);
        const uint2* vp = reinterpret_cast<const uint2*>(g_vh + (size_t)s * DIMC);
        uint2 qr0 = qp[lane], qr1 = qp[lane + 32];
        uint2 vr0 = vp[lane], vr1 = vp[lane + 32];

#pragma unroll 1
        for (int j = beg; j < end; j++) {
            int s2 = (j + 1 < end) ? g_csr[j + 1] : s;
            const uint2* qp2 = reinterpret_cast<const uint2*>(g_qh + (size_t)s2 * DIMC);
            const uint2* vp2 = reinterpret_cast<const uint2*>(g_vh + (size_t)s2 * DIMC);
            uint2 nq0 = qp2[lane], nq1 = qp2[lane + 32];
            uint2 nv0 = vp2[lane], nv1 = vp2[lane + 32];

            float4 q0 = h4_to_f4(qr0), q1 = h4_to_f4(qr1);

            float p0 = q0.x * k0.x + q0.y * k0.y + q0.z * k0.z + q0.w * k0.w;
            float p1 = q1.x * k1.x + q1.y * k1.y + q1.z * k1.z + q1.w * k1.w;
#pragma unroll
            for (int m = 1; m <= 4; m <<= 1) {
                p0 += __shfl_xor_sync(0xffffffffu, p0, m);
                p1 += __shfl_xor_sync(0xffffffffu, p1, m);
            }
            // p0 = score*sqrt32 for head lane>>3; p1 for head lane>>3 + 4;
            // both uniform within the aligned 8-lane group.
            float e0 = exp2f(p0 * cexp);
            float e1 = exp2f(p1 * cexp);

            // Sum over the 4 groups -> all 8 heads, each once.
            float t = e0 + e1;
            t += __shfl_xor_sync(0xffffffffu, t, 8);
            t += __shfl_xor_sync(0xffffffffu, t, 16);
            float inv = 1.0f / t;

            float w0 = e0 * inv;
            float w1 = e1 * inv;

            float4 v0 = h4_to_f4(vr0), v1 = h4_to_f4(vr1);
            a0.x = fmaf(w0, v0.x, a0.x); a0.y = fmaf(w0, v0.y, a0.y);
            a0.z = fmaf(w0, v0.z, a0.z); a0.w = fmaf(w0, v0.w, a0.w);
            a1.x = fmaf(w1, v1.x, a1.x); a1.y = fmaf(w1, v1.y, a1.y);
            a1.z = fmaf(w1, v1.z, a1.z); a1.w = fmaf(w1, v1.w, a1.w);

            qr0 = nq0; qr1 = nq1; vr0 = nv0; vr1 = nv1;
        }
    }

    write_split_half(node, lane, 0, a0);   // chunks 0..7
    write_split_half(node, lane, 8, a1);   // chunks 8..15
}

// ---------------------------------------------------------------------------
// Launch
// ---------------------------------------------------------------------------
extern "C" void kernel_launch(void* const* d_in, const int* in_sizes, int n_in,
                              void* d_out, int out_size)
{
    const float* x   = (const float*)d_in[0];
    const int*   src = (const int*)  d_in[1];
    const int*   dst = (const int*)  d_in[2];
    const float* Wq  = (const float*)d_in[3];
    const float* bq  = (const float*)d_in[4];
    const float* Wk  = (const float*)d_in[5];
    const float* bk  = (const float*)d_in[6];
    const float* Wv  = (const float*)d_in[7];
    const float* bv  = (const float*)d_in[8];
    const float* Wo  = (const float*)d_in[9];
    const float* bo  = (const float*)d_in[10];
    float* out = (float*)d_out;

    int N = in_sizes[0] / DIMC;
    int E = in_sizes[1];

    int mtiles = (N + BM - 1) / BM;   // 79
    int ntiles = DIMC / BN;           // 4

    // 1) prep: split x + split W + dst histogram + counter reset (one launch)
    int splitXBlocks = (N * 16 + 255) / 256;
    int splitWBlocks = (4 * 256 * 16 + 255) / 256;
    int histBlocks   = (E + 255) / 256;
    prep_kernel<<<splitXBlocks + splitWBlocks + histBlocks, 256>>>(
        x, Wq, Wk, Wv, Wo, dst, N, E, splitXBlocks, splitWBlocks);

    // 2) CSR scan
    scan_kernel<<<1, 1024>>>(N);

    // 3) persistent QKV GEMM + fused CSR fill + deg re-zero (one launch)
    int fillBlocks    = (E + 255) / 256;
    int zeroDegBlocks = (MAXN + 255) / 256;
    int qkvTiles = 3 * mtiles * ntiles;
    gemm_qkv_fill_kernel<<<NGEMM + fillBlocks + zeroDegBlocks, 256>>>(
        N, qkvTiles, bq, bk, bv, src, dst, E, fillBlocks);

    // 4) dst-centric attention, fused split epilogue
    edge_csr_kernel<<<(N + 7) / 8, 256>>>(N);

    // 5) persistent output projection
    gemm_out_kernel<<<NGEMM, 256>>>(N, mtiles * ntiles, bo, out);
}